// round 5
// baseline (speedup 1.0000x reference)
#include <cuda_runtime.h>

// B3-spline undecimated wavelet transform (a trous), 3 levels, fully fused.
// x: (8, 1024, 1024) f32 -> out: (8, 4, 1024, 1024) f32 = [w1, w2, w3, c3]
//
// R4: 8-wide per-thread work in both passes (halves LDS + indexing overhead),
// vectorized halo load for interior tiles, 512 threads x 3 CTAs/SM.

#define IMG   1024
#define TS    64
#define HL    14
#define S     (TS + 2*HL)   // 92
#define SP    96            // row stride (16B-aligned rows)
#define NTHR  512
#define SHIFT 2             // phys col = logical col + SHIFT

#define SMEM_FLOATS (2 * S * SP + 8)
#define SMEM_BYTES  (SMEM_FLOATS * sizeof(float))

__device__ __forceinline__ int reflect_idx(int g) {
    if (g < 0) g = -g;
    if (g >= IMG) g = 2 * IMG - 2 - g;
    return g;
}

template<int d, int h, int a>
__device__ __forceinline__ void do_level(float* __restrict__ P,
                                         float* __restrict__ Q,
                                         float* __restrict__ och,
                                         int ty0, int tx0) {
    const float w0 = 0.0625f, w1 = 0.25f, w2 = 0.375f;

    // ---- H-conv (along y): P -> Q. rows [a, S-a), cols [h, S-h). 8-row strips.
    {
        constexpr int rows   = S - 2 * a;      // 88 / 80 / 64
        constexpr int cols   = S - 2 * h;      // 92 / 88 / 80
        constexpr int strips = rows / 8;       // 11 / 10 / 8
        constexpr int nw     = 8 + 4 * d;      // 12 / 16 / 24
        for (int idx = threadIdx.x; idx < strips * cols; idx += NTHR) {
            int x  = idx % cols;
            int t  = idx / cols;
            int y0 = a + 8 * t;
            int oc = h + x + SHIFT;
            int ob = (y0 - 2 * d) * SP + oc;
            float v[nw];
#pragma unroll
            for (int i = 0; i < nw; i++) v[i] = P[ob + i * SP];
#pragma unroll
            for (int i = 0; i < 8; i++) {
                Q[(y0 + i) * SP + oc] = w2 * v[2 * d + i]
                                      + w1 * (v[d + i] + v[3 * d + i])
                                      + w0 * (v[i] + v[4 * d + i]);
            }
        }
    }
    __syncthreads();

    // ---- W-conv (along x): Q -> P in place, emit w_j on center. 8-col groups.
    {
        constexpr int n2  = S - 2 * a;                    // 88 / 80 / 64
        constexpr int xg  = n2 / 8;                       // 11 / 10 / 8
        constexpr int off = (2 * d) & 3;                  // 2 / 0 / 0
        constexpr int nwf = (8 + 4 * d + off + 3) & ~3;   // 16 / 16 / 24
        for (int idx = threadIdx.x; idx < n2 * xg; idx += NTHR) {
            int g  = idx % xg;
            int y  = a + idx / xg;
            int x0 = a + 8 * g;                 // logical
            int op = y * SP + x0 + SHIFT;       // phys, 16B-aligned
            int ow = op - 2 * d - off;          // aligned window start
            float v[nwf];
#pragma unroll
            for (int k = 0; k < nwf / 4; k++) {
                float4 t4 = *reinterpret_cast<const float4*>(&Q[ow + 4 * k]);
                v[4 * k] = t4.x; v[4 * k + 1] = t4.y;
                v[4 * k + 2] = t4.z; v[4 * k + 3] = t4.w;
            }
            float c[8];
#pragma unroll
            for (int i = 0; i < 8; i++) {
                c[i] = w2 * v[off + 2 * d + i]
                     + w1 * (v[off + d + i] + v[off + 3 * d + i])
                     + w0 * (v[off + i] + v[off + 4 * d + i]);
            }
            float4 p0 = *reinterpret_cast<const float4*>(&P[op]);
            float4 p1 = *reinterpret_cast<const float4*>(&P[op + 4]);
            *reinterpret_cast<float4*>(&P[op])     = make_float4(c[0], c[1], c[2], c[3]);
            *reinterpret_cast<float4*>(&P[op + 4]) = make_float4(c[4], c[5], c[6], c[7]);
            bool yok = (a == HL) || (y >= HL && y < S - HL);
            if (yok) {
                int gy = ty0 + y - HL;
                float* orow = och + gy * IMG + (tx0 + x0 - HL);
                if (a == HL || (x0 >= HL && x0 + 4 <= S - HL)) {
                    *reinterpret_cast<float4*>(orow) =
                        make_float4(p0.x - c[0], p0.y - c[1], p0.z - c[2], p0.w - c[3]);
                }
                if (a == HL || (x0 + 4 >= HL && x0 + 8 <= S - HL)) {
                    *reinterpret_cast<float4*>(orow + 4) =
                        make_float4(p1.x - c[4], p1.y - c[5], p1.z - c[6], p1.w - c[7]);
                }
            }
        }
    }
    __syncthreads();
}

__global__ void __launch_bounds__(NTHR, 3) uwt_kernel(const float* __restrict__ x,
                                                      float* __restrict__ out) {
    extern __shared__ float smem[];
    float* P = smem;
    float* Q = smem + S * SP + 4;

    const int b   = blockIdx.z;
    const int ty0 = blockIdx.y * TS;
    const int tx0 = blockIdx.x * TS;
    const float* xb = x + (size_t)b * IMG * IMG;

    // ---- load c0 with halo ----
    const bool interior = (tx0 >= 64 && tx0 <= IMG - TS - 16) &&
                          (ty0 >= 64 && ty0 <= IMG - TS - 16);
    if (interior) {
        // full 96-wide rows (logical cols [-2, 94)), 16B-aligned LDG/STS.128
        const float* src = xb + (size_t)(ty0 - HL) * IMG + (tx0 - 16);
        for (int idx = threadIdx.x; idx < S * (SP / 4); idx += NTHR) {
            int ly = idx / (SP / 4);
            int k  = idx - ly * (SP / 4);
            float4 v4 = *reinterpret_cast<const float4*>(src + (size_t)ly * IMG + 4 * k);
            *reinterpret_cast<float4*>(&P[ly * SP + 4 * k]) = v4;
        }
    } else {
        for (int idx = threadIdx.x; idx < S * S; idx += NTHR) {
            int ly = idx / S;
            int lx = idx - ly * S;
            int gy = reflect_idx(ty0 + ly - HL);
            int gx = reflect_idx(tx0 + lx - HL);
            P[ly * SP + lx + SHIFT] = xb[gy * IMG + gx];
        }
    }
    __syncthreads();

    float* ob = out + (size_t)b * 4 * IMG * IMG;
    do_level<1, 0, 2> (P, Q, ob + 0 * IMG * IMG, ty0, tx0);
    do_level<2, 2, 6> (P, Q, ob + 1 * IMG * IMG, ty0, tx0);
    do_level<4, 6, 14>(P, Q, ob + 2 * IMG * IMG, ty0, tx0);

    // ---- write c3 (channel 3), 8-wide ----
    {
        float* och = ob + 3 * IMG * IMG;
        constexpr int gpr = TS / 8;   // 8 groups per row
        for (int idx = threadIdx.x; idx < TS * gpr; idx += NTHR) {
            int g  = idx % gpr;
            int ly = idx / gpr;
            int pc = (HL + ly) * SP + HL + 8 * g + SHIFT;   // 16B-aligned
            float4 v0 = *reinterpret_cast<const float4*>(&P[pc]);
            float4 v1 = *reinterpret_cast<const float4*>(&P[pc + 4]);
            float* orow = och + (ty0 + ly) * IMG + tx0 + 8 * g;
            *reinterpret_cast<float4*>(orow)     = v0;
            *reinterpret_cast<float4*>(orow + 4) = v1;
        }
    }
}

extern "C" void kernel_launch(void* const* d_in, const int* in_sizes, int n_in,
                              void* d_out, int out_size) {
    const float* x = (const float*)d_in[0];
    float* out     = (float*)d_out;

    cudaFuncSetAttribute(uwt_kernel, cudaFuncAttributeMaxDynamicSharedMemorySize,
                         (int)SMEM_BYTES);

    dim3 grid(IMG / TS, IMG / TS, 8);
    uwt_kernel<<<grid, NTHR, SMEM_BYTES>>>(x, out);
}

// round 8
// speedup vs baseline: 1.2907x; 1.2907x over previous
#include <cuda_runtime.h>

// B3-spline undecimated wavelet transform (a trous), 3 levels, fully fused.
// x: (8, 1024, 1024) f32 -> out: (8, 4, 1024, 1024) f32 = [w1, w2, w3, c3]
//
// R6 hybrid: 8-row H-conv strips (conflict-free scalar LDS, fewer loads/output)
// + 4-col W-conv groups (lanes 16B apart -> conflict-free LDS.128)
// + vectorized interior halo load. 512 threads, 3 CTAs/SM.

#define IMG   1024
#define TS    64
#define HL    14
#define S     (TS + 2*HL)   // 92
#define SP    96            // row stride (16B-aligned rows)
#define NTHR  512
#define SHIFT 2             // phys col = logical col + SHIFT

#define SMEM_FLOATS (2 * S * SP + 8)
#define SMEM_BYTES  (SMEM_FLOATS * sizeof(float))

__device__ __forceinline__ int reflect_idx(int g) {
    if (g < 0) g = -g;
    if (g >= IMG) g = 2 * IMG - 2 - g;
    return g;
}

__device__ __forceinline__ float4 f4_add(float4 a, float4 b) {
    return make_float4(a.x + b.x, a.y + b.y, a.z + b.z, a.w + b.w);
}

template<int d, int h, int a>
__device__ __forceinline__ void do_level(float* __restrict__ P,
                                         float* __restrict__ Q,
                                         float* __restrict__ och,
                                         int ty0, int tx0) {
    const float w0 = 0.0625f, w1 = 0.25f, w2 = 0.375f;

    // ---- H-conv (along y): P -> Q. rows [a, S-a), cols [h, S-h). 8-row strips.
    //      Adjacent lanes -> adjacent columns: conflict-free scalar LDS/STS.
    {
        constexpr int rows   = S - 2 * a;      // 88 / 80 / 64
        constexpr int cols   = S - 2 * h;      // 92 / 88 / 80
        constexpr int strips = rows / 8;       // 11 / 10 / 8
        constexpr int nw     = 8 + 4 * d;      // 12 / 16 / 24
        for (int idx = threadIdx.x; idx < strips * cols; idx += NTHR) {
            int x  = idx % cols;
            int t  = idx / cols;
            int y0 = a + 8 * t;
            int oc = h + x + SHIFT;
            int ob = (y0 - 2 * d) * SP + oc;
            float v[nw];
#pragma unroll
            for (int i = 0; i < nw; i++) v[i] = P[ob + i * SP];
#pragma unroll
            for (int i = 0; i < 8; i++) {
                Q[(y0 + i) * SP + oc] = w2 * v[2 * d + i]
                                      + w1 * (v[d + i] + v[3 * d + i])
                                      + w0 * (v[i] + v[4 * d + i]);
            }
        }
    }
    __syncthreads();

    // ---- W-conv (along x): Q -> P in place, emit w_j on center. 4-col groups.
    //      Adjacent lanes 16B apart: one contiguous 512B span per LDS.128.
    {
        constexpr int n2  = S - 2 * a;                     // 88 / 80 / 64
        constexpr int xg  = n2 / 4;                        // 22 / 20 / 16
        for (int idx = threadIdx.x; idx < n2 * xg; idx += NTHR) {
            int g  = idx % xg;
            int y  = a + idx / xg;
            int x0 = a + 4 * g;                 // logical
            int op = y * SP + x0 + SHIFT;       // phys, 16B-aligned
            float c0, c1, c2, c3;
            if constexpr (d == 4) {
                // taps land exactly on float4 lanes
                float4 A = *reinterpret_cast<const float4*>(&Q[op - 8]);
                float4 B = *reinterpret_cast<const float4*>(&Q[op - 4]);
                float4 C = *reinterpret_cast<const float4*>(&Q[op]);
                float4 D = *reinterpret_cast<const float4*>(&Q[op + 4]);
                float4 E = *reinterpret_cast<const float4*>(&Q[op + 8]);
                float4 AE = f4_add(A, E), BD = f4_add(B, D);
                c0 = w0 * AE.x + w1 * BD.x + w2 * C.x;
                c1 = w0 * AE.y + w1 * BD.y + w2 * C.y;
                c2 = w0 * AE.z + w1 * BD.z + w2 * C.z;
                c3 = w0 * AE.w + w1 * BD.w + w2 * C.w;
            } else {
                constexpr int off = ((a - 2 * d) + SHIFT) & 3;   // 2 (d=1), 0 (d=2)
                constexpr int nw  = (4 * d + 4 + off + 3) & ~3;  // 12 / 12
                int ow = op - 2 * d - off;                        // aligned
                float v[nw];
#pragma unroll
                for (int k = 0; k < nw / 4; k++) {
                    float4 t4 = *reinterpret_cast<const float4*>(&Q[ow + 4 * k]);
                    v[4 * k] = t4.x; v[4 * k + 1] = t4.y;
                    v[4 * k + 2] = t4.z; v[4 * k + 3] = t4.w;
                }
                c0 = w2 * v[off + 2 * d]     + w1 * (v[off + d]     + v[off + 3 * d])
                   + w0 * (v[off]            + v[off + 4 * d]);
                c1 = w2 * v[off + 2 * d + 1] + w1 * (v[off + d + 1] + v[off + 3 * d + 1])
                   + w0 * (v[off + 1]        + v[off + 4 * d + 1]);
                c2 = w2 * v[off + 2 * d + 2] + w1 * (v[off + d + 2] + v[off + 3 * d + 2])
                   + w0 * (v[off + 2]        + v[off + 4 * d + 2]);
                c3 = w2 * v[off + 2 * d + 3] + w1 * (v[off + d + 3] + v[off + 3 * d + 3])
                   + w0 * (v[off + 3]        + v[off + 4 * d + 3]);
            }
            float4 prev = *reinterpret_cast<const float4*>(&P[op]);
            *reinterpret_cast<float4*>(&P[op]) = make_float4(c0, c1, c2, c3);
            bool center = (a == HL) ||
                          (y >= HL && y < S - HL && x0 >= HL && x0 < S - HL);
            if (center) {
                int gy = ty0 + y - HL;
                int gx = tx0 + x0 - HL;
                *reinterpret_cast<float4*>(&och[gy * IMG + gx]) =
                    make_float4(prev.x - c0, prev.y - c1,
                                prev.z - c2, prev.w - c3);
            }
        }
    }
    __syncthreads();
}

__global__ void __launch_bounds__(NTHR, 3) uwt_kernel(const float* __restrict__ x,
                                                      float* __restrict__ out) {
    extern __shared__ float smem[];
    float* P = smem;
    float* Q = smem + S * SP + 4;

    const int b   = blockIdx.z;
    const int ty0 = blockIdx.y * TS;
    const int tx0 = blockIdx.x * TS;
    const float* xb = x + (size_t)b * IMG * IMG;

    // ---- load c0 with halo ----
    const bool interior = (tx0 >= 64 && tx0 <= IMG - TS - 16) &&
                          (ty0 >= 64 && ty0 <= IMG - TS - 16);
    if (interior) {
        // full 96-wide rows (logical cols [-2, 94)), 16B-aligned LDG/STS.128
        const float* src = xb + (size_t)(ty0 - HL) * IMG + (tx0 - 16);
        for (int idx = threadIdx.x; idx < S * (SP / 4); idx += NTHR) {
            int ly = idx / (SP / 4);
            int k  = idx - ly * (SP / 4);
            float4 v4 = *reinterpret_cast<const float4*>(src + (size_t)ly * IMG + 4 * k);
            *reinterpret_cast<float4*>(&P[ly * SP + 4 * k]) = v4;
        }
    } else {
        for (int idx = threadIdx.x; idx < S * S; idx += NTHR) {
            int ly = idx / S;
            int lx = idx - ly * S;
            int gy = reflect_idx(ty0 + ly - HL);
            int gx = reflect_idx(tx0 + lx - HL);
            P[ly * SP + lx + SHIFT] = xb[gy * IMG + gx];
        }
    }
    __syncthreads();

    float* ob = out + (size_t)b * 4 * IMG * IMG;
    do_level<1, 0, 2> (P, Q, ob + 0 * IMG * IMG, ty0, tx0);
    do_level<2, 2, 6> (P, Q, ob + 1 * IMG * IMG, ty0, tx0);
    do_level<4, 6, 14>(P, Q, ob + 2 * IMG * IMG, ty0, tx0);

    // ---- write c3 (channel 3), 4-wide (conflict-free) ----
    {
        float* och = ob + 3 * IMG * IMG;
        constexpr int gpr = TS / 4;   // 16 groups per row
        for (int idx = threadIdx.x; idx < TS * gpr; idx += NTHR) {
            int g  = idx % gpr;
            int ly = idx / gpr;
            int pc = (HL + ly) * SP + HL + 4 * g + SHIFT;   // 16B-aligned
            float4 v = *reinterpret_cast<const float4*>(&P[pc]);
            *reinterpret_cast<float4*>(&och[(ty0 + ly) * IMG + tx0 + 4 * g]) = v;
        }
    }
}

extern "C" void kernel_launch(void* const* d_in, const int* in_sizes, int n_in,
                              void* d_out, int out_size) {
    const float* x = (const float*)d_in[0];
    float* out     = (float*)d_out;

    cudaFuncSetAttribute(uwt_kernel, cudaFuncAttributeMaxDynamicSharedMemorySize,
                         (int)SMEM_BYTES);

    dim3 grid(IMG / TS, IMG / TS, 8);
    uwt_kernel<<<grid, NTHR, SMEM_BYTES>>>(x, out);
}